// round 3
// baseline (speedup 1.0000x reference)
#include <cuda_runtime.h>
#include <math.h>

// Problem constants
#define B_   256
#define T_   200
#define E_   100
#define H_   512
#define G4   2048          // 4*H
#define PAD_TOK 50000
#define NCTA 128

typedef unsigned long long ull;

// ---------------- scratch (device globals; no allocation allowed) ----------------
__device__ float g_G[(size_t)T_ * B_ * G4];   // precomputed layer-0 input gates (incl. bias)
__device__ float g_Gact[B_ * G4];             // per-phase recurrent gate partial
__device__ float g_h0[2][B_ * H_];
__device__ float g_h1[2][B_ * H_];
__device__ float g_c0[B_ * H_];
__device__ float g_c1[B_ * H_];
__device__ float g_pool[B_ * H_];
__device__ int   g_tok[T_ * B_];
__device__ int   g_last[B_];

// grid barrier state
__device__ unsigned int g_count;
__device__ volatile unsigned int g_gen;

// ---------------- f32x2 packed-FMA helpers (sm_103a) ----------------
__device__ __forceinline__ ull ffma2(ull a, ull b, ull c) {
    ull d;
    asm("fma.rn.f32x2 %0, %1, %2, %3;" : "=l"(d) : "l"(a), "l"(b), "l"(c));
    return d;
}
__device__ __forceinline__ float2 unpack2(ull v) {
    float2 f;
    asm("mov.b64 {%0, %1}, %2;" : "=f"(f.x), "=f"(f.y) : "l"(v));
    return f;
}
__device__ __forceinline__ float sigm(float x) { return 1.0f / (1.0f + expf(-x)); }

// ---------------- software grid barrier (128 co-resident CTAs) ----------------
__device__ __forceinline__ void grid_sync() {
    __syncthreads();
    if (threadIdx.x == 0) {
        __threadfence();
        unsigned gen = g_gen;
        if (atomicAdd(&g_count, 1u) == NCTA - 1) {
            g_count = 0;
            __threadfence();
            g_gen = gen + 1;
        } else {
            while (g_gen == gen) { }
            __threadfence();
        }
    }
    __syncthreads();
}

// ---------------- prep: transpose tokens + last non-pad position ----------------
__global__ void prep_kernel(const int* __restrict__ X) {
    __shared__ int red[256];
    int b = blockIdx.x;
    int t = threadIdx.x;
    int cand = -1;
    if (t < T_) {
        int tok = X[b * T_ + t];
        g_tok[t * B_ + b] = tok;
        if (tok != PAD_TOK) cand = t;
    }
    red[t] = cand;
    __syncthreads();
    for (int off = 128; off > 0; off >>= 1) {
        if (t < off) red[t] = max(red[t], red[t + off]);
        __syncthreads();
    }
    if (t == 0) g_last[b] = red[0];
}

// ---------------- init h/c/pool ----------------
__global__ void init_state() {
    int i = blockIdx.x * blockDim.x + threadIdx.x;  // 131072 = B*H
    g_c0[i] = 0.0f;
    g_c1[i] = 0.0f;
    g_h0[0][i] = 0.0f;
    g_h1[0][i] = 0.0f;
    g_pool[i] = -3.402823466e38f;
}

// ---------------- batched embed-gather GEMM (one-shot, full grid) ----------------
__global__ __launch_bounds__(256) void gemm_embed(
    const float* __restrict__ emb,
    const float* __restrict__ Wih,    // [2048][100]
    const float* __restrict__ bias)   // [2048]
{
    __shared__ float As[16][132];
    __shared__ float Bs[16][132];
    const int K = E_;
    int tid = threadIdx.x;
    int j0 = blockIdx.x * 128;
    int m0 = blockIdx.y * 128;
    int lk = tid & 15, lr = tid >> 4;
    int tx = tid & 15, ty = tid >> 4;
    ull acc[8][4];
    #pragma unroll
    for (int i = 0; i < 8; ++i)
        #pragma unroll
        for (int j = 0; j < 4; ++j) acc[i][j] = 0ull;

    for (int k0 = 0; k0 < K; k0 += 16) {
        #pragma unroll
        for (int p = 0; p < 8; ++p) {
            int r  = lr + p * 16;
            int gk = k0 + lk;
            float va = 0.0f, vb = 0.0f;
            if (gk < K) {
                va = emb[(size_t)g_tok[m0 + r] * E_ + gk];
                vb = Wih[(j0 + r) * K + gk];
            }
            As[lk][r] = va;
            Bs[lk][r] = vb;
        }
        __syncthreads();
        #pragma unroll
        for (int kk = 0; kk < 16; ++kk) {
            float4 a0 = *reinterpret_cast<const float4*>(&As[kk][ty * 8]);
            float4 a1 = *reinterpret_cast<const float4*>(&As[kk][ty * 8 + 4]);
            const ull* bp = reinterpret_cast<const ull*>(&Bs[kk][tx * 8]);
            ull b2[4];
            #pragma unroll
            for (int j = 0; j < 4; ++j) b2[j] = bp[j];
            float av[8] = {a0.x, a0.y, a0.z, a0.w, a1.x, a1.y, a1.z, a1.w};
            #pragma unroll
            for (int i = 0; i < 8; ++i) {
                ull a2;
                asm("mov.b64 %0, {%1, %1};" : "=l"(a2) : "f"(av[i]));
                #pragma unroll
                for (int j = 0; j < 4; ++j) acc[i][j] = ffma2(a2, b2[j], acc[i][j]);
            }
        }
        __syncthreads();
    }
    #pragma unroll
    for (int i = 0; i < 8; ++i) {
        int m = m0 + ty * 8 + i;
        float* Crow = g_G + (size_t)m * G4 + j0 + tx * 8;
        #pragma unroll
        for (int j = 0; j < 4; ++j) {
            float2 v = unpack2(acc[i][j]);
            int jj = j0 + tx * 8 + j * 2;
            Crow[j * 2]     = v.x + bias[jj];
            Crow[j * 2 + 1] = v.y + bias[jj + 1];
        }
    }
}

// ---------------- persistent recurrence: whole T loop in one kernel ----------------
// 128 CTAs x 256 threads. Per step, per layer: 64x64 GEMM tile per CTA (f32x2,
// A pre-duplicated in smem so no packing movs), grid barrier, fused combine.
__global__ __launch_bounds__(256) void lstm_persistent(
    const float* __restrict__ Whh0,
    const float* __restrict__ Whh1,
    const float* __restrict__ Wih1,
    const float* __restrict__ bias1)
{
    __shared__ float HsD[16][136];   // A tile, duplicated pairs: 64 rows * 2
    __shared__ float Ws[16][72];     // B tile
    int tid = threadIdx.x;
    int cta = blockIdx.x;
    int ji = cta & 31, bi = cta >> 5;
    int j0 = ji * 64, b0 = bi * 64;
    int lk = tid & 15, lr = tid >> 4;
    int tx = tid & 15, ty = tid >> 4;

    // combine-phase mapping: 1024 consecutive elems per CTA, 4 per thread
    int cbase = cta * 1024 + tid * 4;       // gid of first elem
    int cb = cbase >> 9;                    // batch row
    int cu = cbase & 511;                   // hidden unit (multiple of 4)

    for (int t = 0; t < T_; ++t) {
        int par = t & 1;
        #pragma unroll 1
        for (int layer = 0; layer < 2; ++layer) {
            // ---------------- GEMM phase ----------------
            const float* hA = layer ? g_h1[par] : g_h0[par];
            const float* WA = layer ? Whh1 : Whh0;
            const float* hB = g_h0[par ^ 1];
            int nkb = layer ? 64 : 32;

            ull acc00 = 0, acc01 = 0, acc10 = 0, acc11 = 0;
            ull acc20 = 0, acc21 = 0, acc30 = 0, acc31 = 0;

            #pragma unroll 1
            for (int kb = 0; kb < nkb; ++kb) {
                int k0 = kb * 16;
                const float* hs;
                const float* ws;
                int kk0;
                if (k0 < 512) { hs = hA; ws = WA; kk0 = k0; }
                else          { hs = hB; ws = Wih1; kk0 = k0 - 512; }
                #pragma unroll
                for (int p = 0; p < 4; ++p) {
                    int r = lr + p * 16;
                    float hv = hs[(b0 + r) * H_ + kk0 + lk];
                    HsD[lk][2 * r]     = hv;
                    HsD[lk][2 * r + 1] = hv;
                    Ws[lk][r] = ws[(j0 + r) * H_ + kk0 + lk];
                }
                __syncthreads();
                #pragma unroll
                for (int kk = 0; kk < 16; ++kk) {
                    const ull* ap = reinterpret_cast<const ull*>(&HsD[kk][ty * 8]);
                    ull a0 = ap[0], a1 = ap[1], a2 = ap[2], a3 = ap[3];
                    const ull* bp = reinterpret_cast<const ull*>(&Ws[kk][tx * 4]);
                    ull bv0 = bp[0], bv1 = bp[1];
                    acc00 = ffma2(a0, bv0, acc00); acc01 = ffma2(a0, bv1, acc01);
                    acc10 = ffma2(a1, bv0, acc10); acc11 = ffma2(a1, bv1, acc11);
                    acc20 = ffma2(a2, bv0, acc20); acc21 = ffma2(a2, bv1, acc21);
                    acc30 = ffma2(a3, bv0, acc30); acc31 = ffma2(a3, bv1, acc31);
                }
                __syncthreads();
            }
            {
                ull* Crow0 = reinterpret_cast<ull*>(g_Gact + (size_t)(b0 + ty * 4 + 0) * G4 + j0 + tx * 4);
                ull* Crow1 = reinterpret_cast<ull*>(g_Gact + (size_t)(b0 + ty * 4 + 1) * G4 + j0 + tx * 4);
                ull* Crow2 = reinterpret_cast<ull*>(g_Gact + (size_t)(b0 + ty * 4 + 2) * G4 + j0 + tx * 4);
                ull* Crow3 = reinterpret_cast<ull*>(g_Gact + (size_t)(b0 + ty * 4 + 3) * G4 + j0 + tx * 4);
                Crow0[0] = acc00; Crow0[1] = acc01;
                Crow1[0] = acc10; Crow1[1] = acc11;
                Crow2[0] = acc20; Crow2[1] = acc21;
                Crow3[0] = acc30; Crow3[1] = acc31;
            }
            grid_sync();

            // ---------------- combine phase ----------------
            {
                const float* Ga = g_Gact + (size_t)cb * G4 + cu;
                float4 gi = *reinterpret_cast<const float4*>(Ga);
                float4 gf = *reinterpret_cast<const float4*>(Ga + 512);
                float4 gg = *reinterpret_cast<const float4*>(Ga + 1024);
                float4 go = *reinterpret_cast<const float4*>(Ga + 1536);
                if (layer == 0) {
                    const float* Gb = g_G + ((size_t)t * B_ + cb) * G4 + cu;
                    float4 bi4 = *reinterpret_cast<const float4*>(Gb);
                    float4 bf4 = *reinterpret_cast<const float4*>(Gb + 512);
                    float4 bg4 = *reinterpret_cast<const float4*>(Gb + 1024);
                    float4 bo4 = *reinterpret_cast<const float4*>(Gb + 1536);
                    gi.x += bi4.x; gi.y += bi4.y; gi.z += bi4.z; gi.w += bi4.w;
                    gf.x += bf4.x; gf.y += bf4.y; gf.z += bf4.z; gf.w += bf4.w;
                    gg.x += bg4.x; gg.y += bg4.y; gg.z += bg4.z; gg.w += bg4.w;
                    go.x += bo4.x; go.y += bo4.y; go.z += bo4.z; go.w += bo4.w;
                } else {
                    const float* Bb = bias1 + cu;
                    float4 bi4 = *reinterpret_cast<const float4*>(Bb);
                    float4 bf4 = *reinterpret_cast<const float4*>(Bb + 512);
                    float4 bg4 = *reinterpret_cast<const float4*>(Bb + 1024);
                    float4 bo4 = *reinterpret_cast<const float4*>(Bb + 1536);
                    gi.x += bi4.x; gi.y += bi4.y; gi.z += bi4.z; gi.w += bi4.w;
                    gf.x += bf4.x; gf.y += bf4.y; gf.z += bf4.z; gf.w += bf4.w;
                    gg.x += bg4.x; gg.y += bg4.y; gg.z += bg4.z; gg.w += bg4.w;
                    go.x += bo4.x; go.y += bo4.y; go.z += bo4.z; go.w += bo4.w;
                }
                float* cc = layer ? g_c1 : g_c0;
                float4 c4 = *reinterpret_cast<const float4*>(cc + cbase);
                float4 h4;
                {
                    float ii, ff, ggs, oo, c, h;
                    ii = sigm(gi.x); ff = sigm(gf.x); ggs = tanhf(gg.x); oo = sigm(go.x);
                    c = ff * c4.x + ii * ggs; c4.x = c; h4.x = oo * tanhf(c);
                    ii = sigm(gi.y); ff = sigm(gf.y); ggs = tanhf(gg.y); oo = sigm(go.y);
                    c = ff * c4.y + ii * ggs; c4.y = c; h4.y = oo * tanhf(c);
                    ii = sigm(gi.z); ff = sigm(gf.z); ggs = tanhf(gg.z); oo = sigm(go.z);
                    c = ff * c4.z + ii * ggs; c4.z = c; h4.z = oo * tanhf(c);
                    ii = sigm(gi.w); ff = sigm(gf.w); ggs = tanhf(gg.w); oo = sigm(go.w);
                    c = ff * c4.w + ii * ggs; c4.w = c; h4.w = oo * tanhf(c);
                }
                *reinterpret_cast<float4*>(cc + cbase) = c4;
                if (layer == 0) {
                    *reinterpret_cast<float4*>(g_h0[par ^ 1] + cbase) = h4;
                } else {
                    *reinterpret_cast<float4*>(g_h1[par ^ 1] + cbase) = h4;
                    if (t <= g_last[cb]) {
                        float4 p4 = *reinterpret_cast<const float4*>(g_pool + cbase);
                        p4.x = fmaxf(p4.x, h4.x);
                        p4.y = fmaxf(p4.y, h4.y);
                        p4.z = fmaxf(p4.z, h4.z);
                        p4.w = fmaxf(p4.w, h4.w);
                        *reinterpret_cast<float4*>(g_pool + cbase) = p4;
                    }
                }
            }
            grid_sync();
        }
    }
}

// ---------------- final projection: logits = pool @ W_out^T + b_out ----------------
__global__ void final_kernel(const float* __restrict__ Wout,
                             const float* __restrict__ bout,
                             float* __restrict__ out) {
    int b = blockIdx.x, lane = threadIdx.x;
    float s0 = 0.f, s1 = 0.f, s2 = 0.f, s3 = 0.f, s4 = 0.f;
    for (int u = lane; u < H_; u += 32) {
        float p = g_pool[b * H_ + u];
        s0 += p * Wout[u];
        s1 += p * Wout[512 + u];
        s2 += p * Wout[1024 + u];
        s3 += p * Wout[1536 + u];
        s4 += p * Wout[2048 + u];
    }
    #pragma unroll
    for (int off = 16; off > 0; off >>= 1) {
        s0 += __shfl_down_sync(0xffffffffu, s0, off);
        s1 += __shfl_down_sync(0xffffffffu, s1, off);
        s2 += __shfl_down_sync(0xffffffffu, s2, off);
        s3 += __shfl_down_sync(0xffffffffu, s3, off);
        s4 += __shfl_down_sync(0xffffffffu, s4, off);
    }
    if (lane == 0) {
        out[b * 5 + 0] = s0 + bout[0];
        out[b * 5 + 1] = s1 + bout[1];
        out[b * 5 + 2] = s2 + bout[2];
        out[b * 5 + 3] = s3 + bout[3];
        out[b * 5 + 4] = s4 + bout[4];
    }
}

// ---------------- launch ----------------
extern "C" void kernel_launch(void* const* d_in, const int* in_sizes, int n_in,
                              void* d_out, int out_size) {
    (void)in_sizes; (void)n_in; (void)out_size;
    const int*   X     = (const int*)d_in[0];
    const float* emb   = (const float*)d_in[1];
    const float* W_ih0 = (const float*)d_in[2];
    const float* W_hh0 = (const float*)d_in[3];
    const float* b0    = (const float*)d_in[4];
    const float* W_ih1 = (const float*)d_in[5];
    const float* W_hh1 = (const float*)d_in[6];
    const float* b1    = (const float*)d_in[7];
    const float* W_out = (const float*)d_in[8];
    const float* b_out = (const float*)d_in[9];
    float* out = (float*)d_out;

    prep_kernel<<<B_, 256>>>(X);
    init_state<<<512, 256>>>();
    gemm_embed<<<dim3(G4 / 128, (T_ * B_) / 128), 256>>>(emb, W_ih0, b0);
    lstm_persistent<<<NCTA, 256>>>(W_hh0, W_hh1, W_ih1, b1);
    final_kernel<<<B_, 32>>>(W_out, b_out, out);
}